// round 7
// baseline (speedup 1.0000x reference)
#include <cuda_runtime.h>
#include <cstdint>
#include <float.h>

// Problem constants
constexpr int Bc = 2, Hc = 16, Sc = 2048, Dc = 64;
constexpr int BM = 128, BN = 64;
constexpr int LDH = 72;                  // fp16 tile pitch in halves: bank = 4g+t, conflict-free
constexpr int SP  = 68;                  // fp32 staging pitch in floats
constexpr int STAGE_F   = 64 * SP;       // floats per staged f32 tile (4352)
constexpr int F16TILE_H = 64 * LDH;      // halves per fp16 tile (4608)
// dynamic smem: f32 stage (K+V) + fp16 ping-pong (2 stages x (K + Vt))
constexpr int SMEM_BYTES = 2 * STAGE_F * 4 + 2 * 2 * F16TILE_H * 2;  // 71,680 B
constexpr float SCL = 0.18033688011f;    // 0.125 * log2(e)

// pack two fp32 -> f16x2 (lo = first arg); same convention as R6 (passing).
__device__ __forceinline__ uint32_t pack_f16x2(float lo, float hi) {
    uint32_t r;
    asm("cvt.rn.f16x2.f32 %0, %1, %2;" : "=r"(r) : "f"(hi), "f"(lo));
    return r;
}

__device__ __forceinline__ float ex2(float x) {
    float y;
    asm("ex2.approx.ftz.f32 %0, %1;" : "=f"(y) : "f"(x));
    return y;
}

__device__ __forceinline__ void mma_f16(float c[4], const uint32_t a[4],
                                        uint32_t b0, uint32_t b1) {
    asm volatile(
        "mma.sync.aligned.m16n8k16.row.col.f32.f16.f16.f32 "
        "{%0,%1,%2,%3}, {%4,%5,%6,%7}, {%8,%9}, {%0,%1,%2,%3};"
        : "+f"(c[0]), "+f"(c[1]), "+f"(c[2]), "+f"(c[3])
        : "r"(a[0]), "r"(a[1]), "r"(a[2]), "r"(a[3]), "r"(b0), "r"(b1));
}

__device__ __forceinline__ void cp_async16(uint32_t saddr, const void* gptr) {
    asm volatile("cp.async.cg.shared.global [%0], [%1], 16;" :: "r"(saddr), "l"(gptr));
}

// Flash-attention, fp16 mma.sync m16n8k16 (fp32 accumulate), 2 CTAs/SM,
// cp.async-prefetched K/V: tile jt+1 streams into an fp32 staging buffer
// during tile jt's compute; a cheap smem->smem convert pass then fills the
// fp16 ping-pong buffers. Compute dataflow identical to the R6 kernel.
__global__ __launch_bounds__(256, 2)
void fa_f16_pipe(const float* __restrict__ q, const float* __restrict__ k,
                 const float* __restrict__ v, const float* __restrict__ bias,
                 float* __restrict__ out)
{
    extern __shared__ float sm[];
    float* stK = sm;                  // f32 staging, K tile
    float* stV = sm + STAGE_F;        // f32 staging, V tile
    uint16_t* f16 = reinterpret_cast<uint16_t*>(sm + 2 * STAGE_F);
    const uint32_t stK_s = (uint32_t)__cvta_generic_to_shared(stK);
    const uint32_t stV_s = (uint32_t)__cvta_generic_to_shared(stV);

    const int qt = (int)gridDim.x - 1 - (int)blockIdx.x;  // heavy CTAs first
    const int h = blockIdx.y;
    const int b = blockIdx.z;

    const int tid = threadIdx.x;
    const int wid = tid >> 5;
    const int lane = tid & 31;
    const int g = lane >> 2;
    const int t = lane & 3;
    const int i0w = wid * 16;

    const size_t bh = (size_t)b * Hc + h;
    const float* qb    = q    + (bh * Sc + (size_t)qt * BM) * Dc;
    const float* kb    = k    + bh * Sc * Dc;
    const float* vb    = v    + bh * Sc * Dc;
    const float* biasb = bias + (bh * Sc + (size_t)qt * BM) * Sc;
    float* outb        = out  + (bh * Sc + (size_t)qt * BM) * Dc;

    const int ntiles = 2 * qt + 2;

    // ---- cp.async issue for K/V tile at jbase -> f32 staging ----
    auto issue_kv = [&](int jbase) {
        #pragma unroll
        for (int p = 0; p < 4; p++) {
            const int tt = tid + p * 256;
            const int r = tt >> 4;
            const int c4 = (tt & 15) << 2;
            cp_async16(stK_s + (uint32_t)(r * SP + c4) * 4,
                       kb + (size_t)(jbase + r) * Dc + c4);
            cp_async16(stV_s + (uint32_t)(r * SP + c4) * 4,
                       vb + (size_t)(jbase + r) * Dc + c4);
        }
    };

    // ---- convert staged f32 K/V -> fp16 buffers of pipeline stage s ----
    auto convert_stage = [&](int s) {
        uint16_t* sKh = f16 + s * 2 * F16TILE_H;
        uint32_t* dv  = reinterpret_cast<uint32_t*>(sKh + F16TILE_H);
        // K: thread -> row tid>>2, 16 floats
        {
            const int kr = tid >> 2, kc0 = (tid & 3) << 4;
            const float* src = &stK[kr * SP + kc0];
            float4 f0 = *reinterpret_cast<const float4*>(src);
            float4 f1 = *reinterpret_cast<const float4*>(src + 4);
            float4 f2 = *reinterpret_cast<const float4*>(src + 8);
            float4 f3 = *reinterpret_cast<const float4*>(src + 12);
            uint4 w0, w1;
            w0.x = pack_f16x2(f0.x, f0.y); w0.y = pack_f16x2(f0.z, f0.w);
            w0.z = pack_f16x2(f1.x, f1.y); w0.w = pack_f16x2(f1.z, f1.w);
            w1.x = pack_f16x2(f2.x, f2.y); w1.y = pack_f16x2(f2.z, f2.w);
            w1.z = pack_f16x2(f3.x, f3.y); w1.w = pack_f16x2(f3.z, f3.w);
            uint4* dst = reinterpret_cast<uint4*>(&sKh[kr * LDH + kc0]);
            dst[0] = w0;
            dst[1] = w1;
        }
        // V: transpose into [d][j-pair] words
        {
            const int vjp = tid & 31, vd0 = (tid >> 5) << 3;
            const float* v0p = &stV[(2 * vjp) * SP + vd0];
            const float* v1p = v0p + SP;
            float4 a0 = *reinterpret_cast<const float4*>(v0p);
            float4 a1 = *reinterpret_cast<const float4*>(v0p + 4);
            float4 b0 = *reinterpret_cast<const float4*>(v1p);
            float4 b1 = *reinterpret_cast<const float4*>(v1p + 4);
            dv[(vd0 + 0) * (LDH / 2) + vjp] = pack_f16x2(a0.x, b0.x);
            dv[(vd0 + 1) * (LDH / 2) + vjp] = pack_f16x2(a0.y, b0.y);
            dv[(vd0 + 2) * (LDH / 2) + vjp] = pack_f16x2(a0.z, b0.z);
            dv[(vd0 + 3) * (LDH / 2) + vjp] = pack_f16x2(a0.w, b0.w);
            dv[(vd0 + 4) * (LDH / 2) + vjp] = pack_f16x2(a1.x, b1.x);
            dv[(vd0 + 5) * (LDH / 2) + vjp] = pack_f16x2(a1.y, b1.y);
            dv[(vd0 + 6) * (LDH / 2) + vjp] = pack_f16x2(a1.z, b1.z);
            dv[(vd0 + 7) * (LDH / 2) + vjp] = pack_f16x2(a1.w, b1.w);
        }
    };

    // ---- Prologue: stream tile 0; load Q fragments meanwhile ----
    issue_kv(0);
    asm volatile("cp.async.commit_group;");

    uint32_t qa[4][4];
    #pragma unroll
    for (int ks = 0; ks < 4; ks++) {
        const float* q0 = qb + (size_t)(i0w + g) * Dc + ks * 16 + 2 * t;
        const float* q1 = q0 + (size_t)8 * Dc;
        float2 f;
        f = *reinterpret_cast<const float2*>(q0);     qa[ks][0] = pack_f16x2(f.x, f.y);
        f = *reinterpret_cast<const float2*>(q1);     qa[ks][1] = pack_f16x2(f.x, f.y);
        f = *reinterpret_cast<const float2*>(q0 + 8); qa[ks][2] = pack_f16x2(f.x, f.y);
        f = *reinterpret_cast<const float2*>(q1 + 8); qa[ks][3] = pack_f16x2(f.x, f.y);
    }

    asm volatile("cp.async.wait_group 0;");
    __syncthreads();
    convert_stage(0);
    __syncthreads();
    if (ntiles > 1) issue_kv(BN);
    asm volatile("cp.async.commit_group;");

    // Online-softmax state
    float m[2] = {-FLT_MAX, -FLT_MAX};
    float l[2] = {0.f, 0.f};
    float o[8][4];
    #pragma unroll
    for (int nf = 0; nf < 8; nf++)
        #pragma unroll
        for (int e = 0; e < 4; e++) o[nf][e] = 0.f;

    for (int jt = 0; jt < ntiles; jt++) {
        const int jbase = jt * BN;
        const int cur = jt & 1;
        const bool active = (qt * BM + i0w + 15) >= jbase;

        if (active) {
            const uint16_t* sKh = f16 + cur * 2 * F16TILE_H;
            const uint32_t* sKw = reinterpret_cast<const uint32_t*>(sKh);
            const uint32_t* sVw = reinterpret_cast<const uint32_t*>(sKh + F16TILE_H);

            // ---- Bias prefetch *8 into accumulators ----
            float c[8][4];
            {
                const float* bp0 = biasb + (size_t)(i0w + g) * Sc + jbase + 2 * t;
                const float* bp1 = bp0 + (size_t)8 * Sc;
                #pragma unroll
                for (int nf = 0; nf < 8; nf++) {
                    float2 x0 = *reinterpret_cast<const float2*>(bp0 + nf * 8);
                    float2 x1 = *reinterpret_cast<const float2*>(bp1 + nf * 8);
                    c[nf][0] = x0.x * 8.f;
                    c[nf][1] = x0.y * 8.f;
                    c[nf][2] = x1.x * 8.f;
                    c[nf][3] = x1.y * 8.f;
                }
            }

            // ---- GEMM1: C += Q @ K^T ----
            #pragma unroll
            for (int ks = 0; ks < 4; ks++) {
                #pragma unroll
                for (int nf = 0; nf < 8; nf++) {
                    const int base = (nf * 8 + g) * (LDH / 2) + ks * 8 + t;
                    mma_f16(c[nf], qa[ks], sKw[base], sKw[base + 4]);
                }
            }

            // ---- scale (log2 domain; bias pre-folded), causal mask ----
            #pragma unroll
            for (int nf = 0; nf < 8; nf++)
                #pragma unroll
                for (int e = 0; e < 4; e++) c[nf][e] *= SCL;

            if (jt >= 2 * qt) {
                const int row0 = qt * BM + i0w + g;
                const int row1 = row0 + 8;
                #pragma unroll
                for (int nf = 0; nf < 8; nf++) {
                    const int col = jbase + nf * 8 + 2 * t;
                    if (col     > row0) c[nf][0] = -FLT_MAX;
                    if (col + 1 > row0) c[nf][1] = -FLT_MAX;
                    if (col     > row1) c[nf][2] = -FLT_MAX;
                    if (col + 1 > row1) c[nf][3] = -FLT_MAX;
                }
            }

            // ---- Online softmax ----
            #pragma unroll
            for (int r = 0; r < 2; r++) {
                float rmax = -FLT_MAX;
                #pragma unroll
                for (int nf = 0; nf < 8; nf++)
                    rmax = fmaxf(rmax, fmaxf(c[nf][2 * r], c[nf][2 * r + 1]));
                rmax = fmaxf(rmax, __shfl_xor_sync(0xffffffffu, rmax, 1));
                rmax = fmaxf(rmax, __shfl_xor_sync(0xffffffffu, rmax, 2));
                const float mnew = fmaxf(m[r], rmax);
                const float alpha = ex2(m[r] - mnew);
                float rsum = 0.f;
                #pragma unroll
                for (int nf = 0; nf < 8; nf++) {
                    const float p0 = ex2(c[nf][2 * r]     - mnew);
                    const float p1 = ex2(c[nf][2 * r + 1] - mnew);
                    c[nf][2 * r] = p0;
                    c[nf][2 * r + 1] = p1;
                    rsum += p0 + p1;
                }
                rsum += __shfl_xor_sync(0xffffffffu, rsum, 1);
                rsum += __shfl_xor_sync(0xffffffffu, rsum, 2);
                l[r] = l[r] * alpha + rsum;
                m[r] = mnew;
                #pragma unroll
                for (int nf = 0; nf < 8; nf++) {
                    o[nf][2 * r]     *= alpha;
                    o[nf][2 * r + 1] *= alpha;
                }
            }

            // ---- GEMM2: O += P @ V ----
            #pragma unroll
            for (int ks = 0; ks < 4; ks++) {
                uint32_t pa[4];
                pa[0] = pack_f16x2(c[2 * ks][0],     c[2 * ks][1]);
                pa[1] = pack_f16x2(c[2 * ks][2],     c[2 * ks][3]);
                pa[2] = pack_f16x2(c[2 * ks + 1][0], c[2 * ks + 1][1]);
                pa[3] = pack_f16x2(c[2 * ks + 1][2], c[2 * ks + 1][3]);
                #pragma unroll
                for (int nf = 0; nf < 8; nf++) {
                    const int base = (nf * 8 + g) * (LDH / 2) + ks * 8 + t;
                    mma_f16(o[nf], pa, sVw[base], sVw[base + 4]);
                }
            }
        }

        // ---- Pipeline maintenance (ALL threads; no barrier divergence) ----
        asm volatile("cp.async.wait_group 0;");
        __syncthreads();                        // stage(jt+1) visible; compute(jt) done
        if (jt + 1 < ntiles) convert_stage((jt + 1) & 1);
        __syncthreads();                        // publish fp16(jt+1); staging free
        if (jt + 2 < ntiles) issue_kv((jt + 2) * BN);
        asm volatile("cp.async.commit_group;");
    }

    // ---- Finalize ----
    #pragma unroll
    for (int r = 0; r < 2; r++) {
        const float inv = 1.f / l[r];
        const int row = i0w + g + 8 * r;
        #pragma unroll
        for (int nf = 0; nf < 8; nf++) {
            float2 res = make_float2(o[nf][2 * r] * inv, o[nf][2 * r + 1] * inv);
            *reinterpret_cast<float2*>(outb + (size_t)row * Dc + nf * 8 + 2 * t) = res;
        }
    }
}

extern "C" void kernel_launch(void* const* d_in, const int* in_sizes, int n_in,
                              void* d_out, int out_size)
{
    (void)in_sizes; (void)n_in; (void)out_size;
    const float* q    = (const float*)d_in[0];
    const float* k    = (const float*)d_in[1];
    const float* v    = (const float*)d_in[2];
    const float* bias = (const float*)d_in[3];
    float* out = (float*)d_out;

    cudaFuncSetAttribute(fa_f16_pipe, cudaFuncAttributeMaxDynamicSharedMemorySize,
                         SMEM_BYTES);

    dim3 grid(Sc / BM, Hc, Bc);
    fa_f16_pipe<<<grid, 256, SMEM_BYTES>>>(q, k, v, bias, out);
}